// round 14
// baseline (speedup 1.0000x reference)
#include <cuda_runtime.h>
#include <cstdint>

#define N_NODES 50000
#define E_EDGES 800000
#define NBLK 196            // ceil(50000/256)

// ---------------- scratch (device globals; no allocation allowed) ----------
__device__ __align__(16) float g_z[N_NODES * 64];   // layer-2 left transform
__device__ int g_degi[N_NODES];
__device__ int g_row[N_NODES];
__device__ int g_cur[N_NODES];
__device__ int g_src[E_EDGES];
__device__ int g_dst[E_EDGES];
__device__ int g_csr_src[E_EDGES];
__device__ int g_bsum[NBLK];
__device__ int g_bsumex[NBLK];
__device__ int g_is64;
__device__ int g_cnt;
__device__ int g_flag;
__device__ unsigned g_b1l[128 * 3];   // sign bitmasks: bit=1 => weight>0
__device__ unsigned g_b1r[128 * 3];
__device__ unsigned g_b2l[64 * 4];
__device__ unsigned g_b2r[64 * 4];

// acc += v via FFMA-imm (multiplier = 1.0 immediate -> rt_SMSP=1 path)
__device__ __forceinline__ void facc(float& acc, float v) {
    acc = __fmaf_rn(v, 1.0f, acc);
}

// ---------------- fused init: zero deg/counters + dtype detect + sign pack --
__global__ void k_init(const int* __restrict__ ei32,
                       const float* __restrict__ w1l, const float* __restrict__ w1r,
                       const float* __restrict__ w2l, const float* __restrict__ w2r) {
    int t = blockIdx.x * blockDim.x + threadIdx.x;
    if (t < N_NODES) g_degi[t] = 0;
    if (t == 0) { g_cnt = 0; g_flag = 0; }

    // dtype detect (block 0 only): LE int64 < 2^31 has zero odd words
    if (blockIdx.x == 0) {
        __shared__ int any_nonzero;
        if (threadIdx.x == 0) any_nonzero = 0;
        __syncthreads();
        if (ei32[2 * threadIdx.x + 1] != 0) atomicOr(&any_nonzero, 1);
        __syncthreads();
        if (threadIdx.x == 0) g_is64 = any_nonzero ? 0 : 1;
    }

    // sign pack: one warp per 32-float chunk; 1280 warps total
    int gw   = t >> 5;
    int lane = t & 31;
    if (gw < 1280) {
        const float* src;
        unsigned* dst;
        int w;
        if (gw < 384)       { src = w1l; dst = g_b1l; w = gw; }
        else if (gw < 768)  { src = w1r; dst = g_b1r; w = gw - 384; }
        else if (gw < 1024) { src = w2l; dst = g_b2l; w = gw - 768; }
        else                { src = w2r; dst = g_b2r; w = gw - 1024; }
        unsigned m = __ballot_sync(0xffffffffu, src[w * 32 + lane] > 0.f);
        if (lane == 0) dst[w] = m;
    }
}

// 2 edges per thread, vector loads
__global__ void k_conv(const void* __restrict__ ei) {
    int e = (blockIdx.x * blockDim.x + threadIdx.x) * 2;
    if (e >= E_EDGES) return;
    int s0, s1, d0, d1;
    if (g_is64) {
        const longlong2* ps = (const longlong2*)((const long long*)ei + e);
        const longlong2* pd = (const longlong2*)((const long long*)ei + E_EDGES + e);
        longlong2 vs = *ps, vd = *pd;
        s0 = (int)vs.x; s1 = (int)vs.y;
        d0 = (int)vd.x; d1 = (int)vd.y;
    } else {
        const int2* ps = (const int2*)((const int*)ei + e);
        const int2* pd = (const int2*)((const int*)ei + E_EDGES + e);
        int2 vs = *ps, vd = *pd;
        s0 = vs.x; s1 = vs.y;
        d0 = vd.x; d1 = vd.y;
    }
    s0 = min(max(s0, 0), N_NODES - 1);  s1 = min(max(s1, 0), N_NODES - 1);
    d0 = min(max(d0, 0), N_NODES - 1);  d1 = min(max(d1, 0), N_NODES - 1);
    *(int2*)&g_src[e] = make_int2(s0, s1);
    *(int2*)&g_dst[e] = make_int2(d0, d1);
    atomicAdd(&g_degi[d0], 1);
    atomicAdd(&g_degi[d1], 1);
}

// single-pass exclusive scan of g_degi -> g_row / g_cur (last-block finisher)
__global__ void k_scan() {
    __shared__ int sh[256];
    __shared__ int s_last;
    const int bid = blockIdx.x, tid = threadIdx.x;
    const int i = bid * 256 + tid;
    const int v = (i < N_NODES) ? g_degi[i] : 0;
    sh[tid] = v;
    __syncthreads();
    for (int off = 1; off < 256; off <<= 1) {
        int u = (tid >= off) ? sh[tid - off] : 0;
        __syncthreads();
        sh[tid] += u;
        __syncthreads();
    }
    const int incl = sh[tid];          // inclusive within block
    const int bsum = sh[255];

    if (tid == 0) {
        g_bsum[bid] = bsum;
        __threadfence();
        int old = atomicAdd(&g_cnt, 1);
        s_last = (old == (int)gridDim.x - 1);
    }
    __syncthreads();

    if (s_last) {
        __threadfence();               // acquire: see all g_bsum stores
        int bv = (tid < NBLK) ? g_bsum[tid] : 0;
        sh[tid] = bv;
        __syncthreads();
        for (int off = 1; off < 256; off <<= 1) {
            int u = (tid >= off) ? sh[tid - off] : 0;
            __syncthreads();
            sh[tid] += u;
            __syncthreads();
        }
        if (tid < NBLK) g_bsumex[tid] = sh[tid] - bv;   // exclusive
        __threadfence();
        if (tid == 0) atomicExch(&g_flag, 1);
    } else {
        if (tid == 0) {
            while (atomicAdd(&g_flag, 0) == 0) __nanosleep(64);
        }
        __syncthreads();
        __threadfence();
    }

    if (i < N_NODES) {
        int r = g_bsumex[bid] + incl - v;   // global exclusive prefix
        g_row[i] = r;
        g_cur[i] = r;
    }
}

// 2 edges per thread, int2 index loads
__global__ void k_bucket() {
    int e = (blockIdx.x * blockDim.x + threadIdx.x) * 2;
    if (e >= E_EDGES) return;
    int2 s = *(const int2*)&g_src[e];
    int2 d = *(const int2*)&g_dst[e];
    int p0 = atomicAdd(&g_cur[d.x], 1);
    int p1 = atomicAdd(&g_cur[d.y], 1);
    g_csr_src[min(p0, E_EDGES - 1)] = s.x;
    g_csr_src[min(p1, E_EDGES - 1)] = s.y;
}

// ---------------- fused layer1 + layer2 transform (4 nodes / block) ----------
__global__ void __launch_bounds__(128) k_sage1(const float* __restrict__ x,
                                               const float* __restrict__ bias1,
                                               const float* __restrict__ bias2,
                                               float* __restrict__ outp) {
    constexpr int IN = 96, OUT = 128, NPB = 4, W = 3, F4 = IN / 4;
    __shared__ float4 s_a4[NPB][F4];       // normalized neighbor mean
    __shared__ float4 s_x4[NPB][F4];       // own features
    __shared__ float4 s_h4[NPB][OUT / 4];  // hidden activations (block-local)
    __shared__ float  s_Ta[NPB], s_Tx[NPB], s_Th[NPB];
    __shared__ int    s_start[NPB], s_deg[NPB];

    const int o  = threadIdx.x;
    const int n0 = blockIdx.x * NPB;

    if (o < NPB) {
        s_start[o] = g_row[n0 + o];
        s_deg[o]   = g_degi[n0 + o];
    }
    for (int idx = o; idx < NPB * F4; idx += OUT) {
        int ni = idx / F4, c = idx - ni * F4;
        s_x4[ni][c] = ((const float4*)x)[(size_t)(n0 + ni) * F4 + c];
    }
    __syncthreads();

    // float4 gather-aggregate: thread -> (node, float4 chunk); 96 active lanes
    if (o < NPB * F4) {
        int ni = o / F4, c4 = o - ni * F4;
        int st = s_start[ni], dg = s_deg[ni];
        const float4* x4 = (const float4*)x;
        float4 a0 = make_float4(0.f, 0.f, 0.f, 0.f);
        float4 a1 = a0, a2 = a0, a3 = a0;
        int j = 0;
        for (; j + 4 <= dg; j += 4) {
            int i0 = g_csr_src[st + j + 0];
            int i1 = g_csr_src[st + j + 1];
            int i2 = g_csr_src[st + j + 2];
            int i3 = g_csr_src[st + j + 3];
            float4 v0 = x4[(size_t)i0 * F4 + c4];
            float4 v1 = x4[(size_t)i1 * F4 + c4];
            float4 v2 = x4[(size_t)i2 * F4 + c4];
            float4 v3 = x4[(size_t)i3 * F4 + c4];
            a0.x += v0.x; a0.y += v0.y; a0.z += v0.z; a0.w += v0.w;
            a1.x += v1.x; a1.y += v1.y; a1.z += v1.z; a1.w += v1.w;
            a2.x += v2.x; a2.y += v2.y; a2.z += v2.z; a2.w += v2.w;
            a3.x += v3.x; a3.y += v3.y; a3.z += v3.z; a3.w += v3.w;
        }
        for (; j < dg; ++j) {
            float4 v = x4[(size_t)g_csr_src[st + j] * F4 + c4];
            a0.x += v.x; a0.y += v.y; a0.z += v.z; a0.w += v.w;
        }
        float inv = 1.f / fmaxf((float)dg, 1.f);
        float4 res;
        res.x = (a0.x + a1.x + a2.x + a3.x) * inv;
        res.y = (a0.y + a1.y + a2.y + a3.y) * inv;
        res.z = (a0.z + a1.z + a2.z + a3.z) * inv;
        res.w = (a0.w + a1.w + a2.w + a3.w) * inv;
        s_a4[ni][c4] = res;
    }
    __syncthreads();

    // per-node row totals of a and x (warp ni reduces node ni)
    {
        int lane = o & 31, warp = o >> 5;
        const float* va = (const float*)s_a4[warp];
        const float* vx = (const float*)s_x4[warp];
        float ta = 0.f, tx = 0.f;
#pragma unroll
        for (int f = lane; f < IN; f += 32) { ta += va[f]; tx += vx[f]; }
#pragma unroll
        for (int off = 16; off; off >>= 1) {
            ta += __shfl_xor_sync(0xffffffffu, ta, off);
            tx += __shfl_xor_sync(0xffffffffu, tx, off);
        }
        if (lane == 0) { s_Ta[warp] = ta; s_Tx[warp] = tx; }
    }
    __syncthreads();

    // ---- layer-1 binarized linear ----
    {
        unsigned bl[W], br[W];
#pragma unroll
        for (int w = 0; w < W; ++w) { bl[w] = g_b1l[o * W + w]; br[w] = g_b1r[o * W + w]; }
        const float b = bias1[o];

        float La[NPB], Lb[NPB], Ra[NPB], Rb[NPB];
#pragma unroll
        for (int ni = 0; ni < NPB; ++ni) { La[ni] = Lb[ni] = Ra[ni] = Rb[ni] = 0.f; }

#pragma unroll
        for (int w = 0; w < W; ++w) {
            unsigned l = bl[w], r = br[w];
#pragma unroll
            for (int k = 0; k < 32; k += 4) {
                int c4 = (w * 32 + k) >> 2;
                bool pl0 = (l >> k) & 1u, pl1 = (l >> (k + 1)) & 1u;
                bool pl2 = (l >> (k + 2)) & 1u, pl3 = (l >> (k + 3)) & 1u;
                bool pr0 = (r >> k) & 1u, pr1 = (r >> (k + 1)) & 1u;
                bool pr2 = (r >> (k + 2)) & 1u, pr3 = (r >> (k + 3)) & 1u;
#pragma unroll
                for (int ni = 0; ni < NPB; ++ni) {
                    float4 va = s_a4[ni][c4];
                    float4 vx = s_x4[ni][c4];
                    if (pl0) facc(La[ni], va.x);
                    if (pl1) facc(Lb[ni], va.y);
                    if (pl2) facc(La[ni], va.z);
                    if (pl3) facc(Lb[ni], va.w);
                    if (pr0) facc(Ra[ni], vx.x);
                    if (pr1) facc(Rb[ni], vx.y);
                    if (pr2) facc(Ra[ni], vx.z);
                    if (pr3) facc(Rb[ni], vx.w);
                }
            }
        }
#pragma unroll
        for (int ni = 0; ni < NPB; ++ni) {
            float res = (2.f * (La[ni] + Lb[ni]) - s_Ta[ni]) + b
                      + (2.f * (Ra[ni] + Rb[ni]) - s_Tx[ni]);
            ((float*)s_h4[ni])[o] = fmaxf(res, 0.f);
        }
    }
    __syncthreads();

    // per-node totals of h
    {
        int lane = o & 31, warp = o >> 5;
        const float* vh = (const float*)s_h4[warp];
        float t = 0.f;
#pragma unroll
        for (int f = lane; f < OUT; f += 32) t += vh[f];
#pragma unroll
        for (int off = 16; off; off >>= 1) t += __shfl_xor_sync(0xffffffffu, t, off);
        if (lane == 0) s_Th[warp] = t;
    }
    __syncthreads();

    // ---- layer-2 dual binarized transform (fused) ----
    // 128 threads = 2 groups x 64 output cols; group g handles nodes {2g, 2g+1}
    {
        constexpr int W2 = 4;
        const int grp = o >> 6;
        const int oc  = o & 63;
        unsigned bl[W2], br[W2];
#pragma unroll
        for (int w = 0; w < W2; ++w) { bl[w] = g_b2l[oc * W2 + w]; br[w] = g_b2r[oc * W2 + w]; }
        const float b = bias2[oc];

        float La[2], Lb[2], Ra[2], Rb[2];
#pragma unroll
        for (int q = 0; q < 2; ++q) { La[q] = Lb[q] = Ra[q] = Rb[q] = 0.f; }

#pragma unroll
        for (int w = 0; w < W2; ++w) {
            unsigned l = bl[w], r = br[w];
#pragma unroll
            for (int k = 0; k < 32; k += 4) {
                int c4 = (w * 32 + k) >> 2;
                bool pl0 = (l >> k) & 1u, pl1 = (l >> (k + 1)) & 1u;
                bool pl2 = (l >> (k + 2)) & 1u, pl3 = (l >> (k + 3)) & 1u;
                bool pr0 = (r >> k) & 1u, pr1 = (r >> (k + 1)) & 1u;
                bool pr2 = (r >> (k + 2)) & 1u, pr3 = (r >> (k + 3)) & 1u;
#pragma unroll
                for (int q = 0; q < 2; ++q) {
                    float4 vh = s_h4[2 * grp + q][c4];
                    if (pl0) facc(La[q], vh.x);
                    if (pl1) facc(Lb[q], vh.y);
                    if (pl2) facc(La[q], vh.z);
                    if (pl3) facc(Lb[q], vh.w);
                    if (pr0) facc(Ra[q], vh.x);
                    if (pr1) facc(Rb[q], vh.y);
                    if (pr2) facc(Ra[q], vh.z);
                    if (pr3) facc(Rb[q], vh.w);
                }
            }
        }
#pragma unroll
        for (int q = 0; q < 2; ++q) {
            int ni = 2 * grp + q;
            float T = s_Th[ni];
            g_z[(size_t)(n0 + ni) * 64 + oc]  = 2.f * (La[q] + Lb[q]) - T;
            outp[(size_t)(n0 + ni) * 64 + oc] = 2.f * (Ra[q] + Rb[q]) - T + b;
        }
    }
}

// ---------------- layer 2b: float4 gather-aggregate of z ---------------------
// 16 nodes x 16 float4-chunks per 256-thread block
__global__ void __launch_bounds__(256) k_agg2(float* __restrict__ outp) {
    constexpr int F4 = 16, NPB = 16;
    __shared__ int s_start[NPB], s_deg[NPB];
    const int t  = threadIdx.x;
    const int n0 = blockIdx.x * NPB;
    if (t < NPB) {
        s_start[t] = g_row[n0 + t];
        s_deg[t]   = g_degi[n0 + t];
    }
    __syncthreads();
    int ni = t >> 4, c4 = t & 15;
    int st = s_start[ni], dg = s_deg[ni];
    const float4* z4 = (const float4*)g_z;
    float4 a0 = make_float4(0.f, 0.f, 0.f, 0.f);
    float4 a1 = a0, a2 = a0, a3 = a0;
    int j = 0;
    for (; j + 4 <= dg; j += 4) {
        int i0 = g_csr_src[st + j + 0];
        int i1 = g_csr_src[st + j + 1];
        int i2 = g_csr_src[st + j + 2];
        int i3 = g_csr_src[st + j + 3];
        float4 v0 = z4[(size_t)i0 * F4 + c4];
        float4 v1 = z4[(size_t)i1 * F4 + c4];
        float4 v2 = z4[(size_t)i2 * F4 + c4];
        float4 v3 = z4[(size_t)i3 * F4 + c4];
        a0.x += v0.x; a0.y += v0.y; a0.z += v0.z; a0.w += v0.w;
        a1.x += v1.x; a1.y += v1.y; a1.z += v1.z; a1.w += v1.w;
        a2.x += v2.x; a2.y += v2.y; a2.z += v2.z; a2.w += v2.w;
        a3.x += v3.x; a3.y += v3.y; a3.z += v3.z; a3.w += v3.w;
    }
    for (; j < dg; ++j) {
        float4 v = z4[(size_t)g_csr_src[st + j] * F4 + c4];
        a0.x += v.x; a0.y += v.y; a0.z += v.z; a0.w += v.w;
    }
    float inv = 1.f / fmaxf((float)dg, 1.f);
    float4* o4 = (float4*)outp;
    size_t oi = (size_t)(n0 + ni) * F4 + c4;
    float4 cur = o4[oi];
    cur.x += (a0.x + a1.x + a2.x + a3.x) * inv;
    cur.y += (a0.y + a1.y + a2.y + a3.y) * inv;
    cur.z += (a0.z + a1.z + a2.z + a3.z) * inv;
    cur.w += (a0.w + a1.w + a2.w + a3.w) * inv;
    o4[oi] = cur;
}

// ---------------- launch ----------------------------------------------------
extern "C" void kernel_launch(void* const* d_in, const int* in_sizes, int n_in,
                              void* d_out, int out_size) {
    const float* x   = (const float*)d_in[0];
    const void*  ei  = d_in[1];
    const float* w1l = (const float*)d_in[2];
    const float* b1  = (const float*)d_in[3];
    const float* w1r = (const float*)d_in[4];
    const float* w2l = (const float*)d_in[5];
    const float* b2  = (const float*)d_in[6];
    const float* w2r = (const float*)d_in[7];
    float*       out = (float*)d_out;

    k_init<<<NBLK, 256>>>((const int*)ei, w1l, w1r, w2l, w2r);
    k_conv<<<(E_EDGES / 2 + 255) / 256, 256>>>(ei);
    k_scan<<<NBLK, 256>>>();
    k_bucket<<<(E_EDGES / 2 + 255) / 256, 256>>>();
    k_sage1<<<N_NODES / 4, 128>>>(x, b1, b2, out);
    k_agg2<<<N_NODES / 16, 256>>>(out);
}

// round 16
// speedup vs baseline: 1.0588x; 1.0588x over previous
#include <cuda_runtime.h>
#include <cstdint>

#define N_NODES 50000
#define E_EDGES 800000
#define NBLK 196            // ceil(50000/256)

// ---------------- scratch (device globals; no allocation allowed) ----------
__device__ __align__(16) float g_z[N_NODES * 64];   // layer-2 left transform
__device__ int g_degi[N_NODES];
__device__ int g_row[N_NODES];
__device__ int g_cur[N_NODES];
__device__ int g_csr_src[E_EDGES];
__device__ int g_bsum[NBLK];
__device__ int g_bsumex[NBLK];
__device__ int g_is64;
__device__ unsigned g_b1l[128 * 3];   // sign bitmasks: bit=1 => weight>0
__device__ unsigned g_b1r[128 * 3];
__device__ unsigned g_b2l[64 * 4];
__device__ unsigned g_b2r[64 * 4];

// acc += v via FFMA-imm (multiplier = 1.0 immediate -> rt_SMSP=1 path)
__device__ __forceinline__ void facc(float& acc, float v) {
    acc = __fmaf_rn(v, 1.0f, acc);
}

// ---------------- fused init: zero degrees + dtype detect + sign pack -------
__global__ void k_init(const int* __restrict__ ei32,
                       const float* __restrict__ w1l, const float* __restrict__ w1r,
                       const float* __restrict__ w2l, const float* __restrict__ w2r) {
    int t = blockIdx.x * blockDim.x + threadIdx.x;
    if (t < N_NODES) g_degi[t] = 0;

    // dtype detect (block 0 only): LE int64 < 2^31 has zero odd words
    if (blockIdx.x == 0) {
        __shared__ int any_nonzero;
        if (threadIdx.x == 0) any_nonzero = 0;
        __syncthreads();
        if (ei32[2 * threadIdx.x + 1] != 0) atomicOr(&any_nonzero, 1);
        __syncthreads();
        if (threadIdx.x == 0) g_is64 = any_nonzero ? 0 : 1;
    }

    // sign pack: one warp per 32-float chunk; 1280 warps total
    int gw   = t >> 5;
    int lane = t & 31;
    if (gw < 1280) {
        const float* src;
        unsigned* dst;
        int w;
        if (gw < 384)       { src = w1l; dst = g_b1l; w = gw; }
        else if (gw < 768)  { src = w1r; dst = g_b1r; w = gw - 384; }
        else if (gw < 1024) { src = w2l; dst = g_b2l; w = gw - 768; }
        else                { src = w2r; dst = g_b2r; w = gw - 1024; }
        unsigned m = __ballot_sync(0xffffffffu, src[w * 32 + lane] > 0.f);
        if (lane == 0) dst[w] = m;
    }
}

// degree count: reads ONLY the dst half of edge_index (2 edges/thread)
__global__ void k_deg(const void* __restrict__ ei) {
    int e = (blockIdx.x * blockDim.x + threadIdx.x) * 2;
    if (e >= E_EDGES) return;
    int d0, d1;
    if (g_is64) {
        longlong2 vd = *(const longlong2*)((const long long*)ei + E_EDGES + e);
        d0 = (int)vd.x; d1 = (int)vd.y;
    } else {
        int2 vd = *(const int2*)((const int*)ei + E_EDGES + e);
        d0 = vd.x; d1 = vd.y;
    }
    d0 = min(max(d0, 0), N_NODES - 1);
    d1 = min(max(d1, 0), N_NODES - 1);
    atomicAdd(&g_degi[d0], 1);
    atomicAdd(&g_degi[d1], 1);
}

// 3-step exclusive scan of g_degi -> g_row / g_cur
__global__ void k_scanA() {
    __shared__ int sh[256];
    int i = blockIdx.x * 256 + threadIdx.x;
    sh[threadIdx.x] = (i < N_NODES) ? g_degi[i] : 0;
    __syncthreads();
    for (int off = 128; off; off >>= 1) {
        if (threadIdx.x < off) sh[threadIdx.x] += sh[threadIdx.x + off];
        __syncthreads();
    }
    if (threadIdx.x == 0) g_bsum[blockIdx.x] = sh[0];
}
__global__ void k_scanB() {      // parallel exclusive scan over NBLK<=256 sums
    __shared__ int sh[256];
    int t = threadIdx.x;
    int v = (t < NBLK) ? g_bsum[t] : 0;
    sh[t] = v;
    __syncthreads();
    for (int off = 1; off < 256; off <<= 1) {
        int u = (t >= off) ? sh[t - off] : 0;
        __syncthreads();
        sh[t] += u;
        __syncthreads();
    }
    if (t < NBLK) g_bsumex[t] = sh[t] - v;   // exclusive
}
__global__ void k_scanC() {
    __shared__ int sh[256];
    int i = blockIdx.x * 256 + threadIdx.x;
    int v = (i < N_NODES) ? g_degi[i] : 0;
    sh[threadIdx.x] = v;
    __syncthreads();
    for (int off = 1; off < 256; off <<= 1) {
        int u = (threadIdx.x >= off) ? sh[threadIdx.x - off] : 0;
        __syncthreads();
        sh[threadIdx.x] += u;
        __syncthreads();
    }
    if (i < N_NODES) {
        int r = g_bsumex[blockIdx.x] + sh[threadIdx.x] - v;   // exclusive
        g_row[i] = r;
        g_cur[i] = r;
    }
}

// CSR fill: reads edge_index directly (2 edges/thread), scatters src by dst
__global__ void k_fill(const void* __restrict__ ei) {
    int e = (blockIdx.x * blockDim.x + threadIdx.x) * 2;
    if (e >= E_EDGES) return;
    int s0, s1, d0, d1;
    if (g_is64) {
        longlong2 vs = *(const longlong2*)((const long long*)ei + e);
        longlong2 vd = *(const longlong2*)((const long long*)ei + E_EDGES + e);
        s0 = (int)vs.x; s1 = (int)vs.y;
        d0 = (int)vd.x; d1 = (int)vd.y;
    } else {
        int2 vs = *(const int2*)((const int*)ei + e);
        int2 vd = *(const int2*)((const int*)ei + E_EDGES + e);
        s0 = vs.x; s1 = vs.y;
        d0 = vd.x; d1 = vd.y;
    }
    s0 = min(max(s0, 0), N_NODES - 1);  s1 = min(max(s1, 0), N_NODES - 1);
    d0 = min(max(d0, 0), N_NODES - 1);  d1 = min(max(d1, 0), N_NODES - 1);
    int p0 = atomicAdd(&g_cur[d0], 1);
    int p1 = atomicAdd(&g_cur[d1], 1);
    g_csr_src[min(p0, E_EDGES - 1)] = s0;
    g_csr_src[min(p1, E_EDGES - 1)] = s1;
}

// ---------------- fused layer1 + layer2 transform (4 nodes / block) ----------
__global__ void __launch_bounds__(128) k_sage1(const float* __restrict__ x,
                                               const float* __restrict__ bias1,
                                               const float* __restrict__ bias2,
                                               float* __restrict__ outp) {
    constexpr int IN = 96, OUT = 128, NPB = 4, W = 3, F4 = IN / 4;
    __shared__ float4 s_a4[NPB][F4];       // normalized neighbor mean
    __shared__ float4 s_x4[NPB][F4];       // own features
    __shared__ float4 s_h4[NPB][OUT / 4];  // hidden activations (block-local)
    __shared__ float  s_Ta[NPB], s_Tx[NPB], s_Th[NPB];
    __shared__ int    s_start[NPB], s_deg[NPB];

    const int o  = threadIdx.x;
    const int n0 = blockIdx.x * NPB;

    if (o < NPB) {
        s_start[o] = g_row[n0 + o];
        s_deg[o]   = g_degi[n0 + o];
    }
    for (int idx = o; idx < NPB * F4; idx += OUT) {
        int ni = idx / F4, c = idx - ni * F4;
        s_x4[ni][c] = ((const float4*)x)[(size_t)(n0 + ni) * F4 + c];
    }
    __syncthreads();

    // float4 gather-aggregate: thread -> (node, float4 chunk); 96 active lanes
    if (o < NPB * F4) {
        int ni = o / F4, c4 = o - ni * F4;
        int st = s_start[ni], dg = s_deg[ni];
        const float4* x4 = (const float4*)x;
        float4 a0 = make_float4(0.f, 0.f, 0.f, 0.f);
        float4 a1 = a0, a2 = a0, a3 = a0;
        int j = 0;
        for (; j + 4 <= dg; j += 4) {
            int i0 = g_csr_src[st + j + 0];
            int i1 = g_csr_src[st + j + 1];
            int i2 = g_csr_src[st + j + 2];
            int i3 = g_csr_src[st + j + 3];
            float4 v0 = x4[(size_t)i0 * F4 + c4];
            float4 v1 = x4[(size_t)i1 * F4 + c4];
            float4 v2 = x4[(size_t)i2 * F4 + c4];
            float4 v3 = x4[(size_t)i3 * F4 + c4];
            a0.x += v0.x; a0.y += v0.y; a0.z += v0.z; a0.w += v0.w;
            a1.x += v1.x; a1.y += v1.y; a1.z += v1.z; a1.w += v1.w;
            a2.x += v2.x; a2.y += v2.y; a2.z += v2.z; a2.w += v2.w;
            a3.x += v3.x; a3.y += v3.y; a3.z += v3.z; a3.w += v3.w;
        }
        for (; j < dg; ++j) {
            float4 v = x4[(size_t)g_csr_src[st + j] * F4 + c4];
            a0.x += v.x; a0.y += v.y; a0.z += v.z; a0.w += v.w;
        }
        float inv = 1.f / fmaxf((float)dg, 1.f);
        float4 res;
        res.x = (a0.x + a1.x + a2.x + a3.x) * inv;
        res.y = (a0.y + a1.y + a2.y + a3.y) * inv;
        res.z = (a0.z + a1.z + a2.z + a3.z) * inv;
        res.w = (a0.w + a1.w + a2.w + a3.w) * inv;
        s_a4[ni][c4] = res;
    }
    __syncthreads();

    // per-node row totals of a and x (warp ni reduces node ni)
    {
        int lane = o & 31, warp = o >> 5;
        const float* va = (const float*)s_a4[warp];
        const float* vx = (const float*)s_x4[warp];
        float ta = 0.f, tx = 0.f;
#pragma unroll
        for (int f = lane; f < IN; f += 32) { ta += va[f]; tx += vx[f]; }
#pragma unroll
        for (int off = 16; off; off >>= 1) {
            ta += __shfl_xor_sync(0xffffffffu, ta, off);
            tx += __shfl_xor_sync(0xffffffffu, tx, off);
        }
        if (lane == 0) { s_Ta[warp] = ta; s_Tx[warp] = tx; }
    }
    __syncthreads();

    // ---- layer-1 binarized linear ----
    {
        unsigned bl[W], br[W];
#pragma unroll
        for (int w = 0; w < W; ++w) { bl[w] = g_b1l[o * W + w]; br[w] = g_b1r[o * W + w]; }
        const float b = bias1[o];

        float La[NPB], Lb[NPB], Ra[NPB], Rb[NPB];
#pragma unroll
        for (int ni = 0; ni < NPB; ++ni) { La[ni] = Lb[ni] = Ra[ni] = Rb[ni] = 0.f; }

#pragma unroll
        for (int w = 0; w < W; ++w) {
            unsigned l = bl[w], r = br[w];
#pragma unroll
            for (int k = 0; k < 32; k += 4) {
                int c4 = (w * 32 + k) >> 2;
                bool pl0 = (l >> k) & 1u, pl1 = (l >> (k + 1)) & 1u;
                bool pl2 = (l >> (k + 2)) & 1u, pl3 = (l >> (k + 3)) & 1u;
                bool pr0 = (r >> k) & 1u, pr1 = (r >> (k + 1)) & 1u;
                bool pr2 = (r >> (k + 2)) & 1u, pr3 = (r >> (k + 3)) & 1u;
#pragma unroll
                for (int ni = 0; ni < NPB; ++ni) {
                    float4 va = s_a4[ni][c4];
                    float4 vx = s_x4[ni][c4];
                    if (pl0) facc(La[ni], va.x);
                    if (pl1) facc(Lb[ni], va.y);
                    if (pl2) facc(La[ni], va.z);
                    if (pl3) facc(Lb[ni], va.w);
                    if (pr0) facc(Ra[ni], vx.x);
                    if (pr1) facc(Rb[ni], vx.y);
                    if (pr2) facc(Ra[ni], vx.z);
                    if (pr3) facc(Rb[ni], vx.w);
                }
            }
        }
#pragma unroll
        for (int ni = 0; ni < NPB; ++ni) {
            float res = (2.f * (La[ni] + Lb[ni]) - s_Ta[ni]) + b
                      + (2.f * (Ra[ni] + Rb[ni]) - s_Tx[ni]);
            ((float*)s_h4[ni])[o] = fmaxf(res, 0.f);
        }
    }
    __syncthreads();

    // per-node totals of h
    {
        int lane = o & 31, warp = o >> 5;
        const float* vh = (const float*)s_h4[warp];
        float t = 0.f;
#pragma unroll
        for (int f = lane; f < OUT; f += 32) t += vh[f];
#pragma unroll
        for (int off = 16; off; off >>= 1) t += __shfl_xor_sync(0xffffffffu, t, off);
        if (lane == 0) s_Th[warp] = t;
    }
    __syncthreads();

    // ---- layer-2 dual binarized transform (fused) ----
    // 128 threads = 2 groups x 64 output cols; group g handles nodes {2g, 2g+1}
    {
        constexpr int W2 = 4;
        const int grp = o >> 6;
        const int oc  = o & 63;
        unsigned bl[W2], br[W2];
#pragma unroll
        for (int w = 0; w < W2; ++w) { bl[w] = g_b2l[oc * W2 + w]; br[w] = g_b2r[oc * W2 + w]; }
        const float b = bias2[oc];

        float La[2], Lb[2], Ra[2], Rb[2];
#pragma unroll
        for (int q = 0; q < 2; ++q) { La[q] = Lb[q] = Ra[q] = Rb[q] = 0.f; }

#pragma unroll
        for (int w = 0; w < W2; ++w) {
            unsigned l = bl[w], r = br[w];
#pragma unroll
            for (int k = 0; k < 32; k += 4) {
                int c4 = (w * 32 + k) >> 2;
                bool pl0 = (l >> k) & 1u, pl1 = (l >> (k + 1)) & 1u;
                bool pl2 = (l >> (k + 2)) & 1u, pl3 = (l >> (k + 3)) & 1u;
                bool pr0 = (r >> k) & 1u, pr1 = (r >> (k + 1)) & 1u;
                bool pr2 = (r >> (k + 2)) & 1u, pr3 = (r >> (k + 3)) & 1u;
#pragma unroll
                for (int q = 0; q < 2; ++q) {
                    float4 vh = s_h4[2 * grp + q][c4];
                    if (pl0) facc(La[q], vh.x);
                    if (pl1) facc(Lb[q], vh.y);
                    if (pl2) facc(La[q], vh.z);
                    if (pl3) facc(Lb[q], vh.w);
                    if (pr0) facc(Ra[q], vh.x);
                    if (pr1) facc(Rb[q], vh.y);
                    if (pr2) facc(Ra[q], vh.z);
                    if (pr3) facc(Rb[q], vh.w);
                }
            }
        }
#pragma unroll
        for (int q = 0; q < 2; ++q) {
            int ni = 2 * grp + q;
            float T = s_Th[ni];
            g_z[(size_t)(n0 + ni) * 64 + oc]  = 2.f * (La[q] + Lb[q]) - T;
            outp[(size_t)(n0 + ni) * 64 + oc] = 2.f * (Ra[q] + Rb[q]) - T + b;
        }
    }
}

// ---------------- layer 2b: float4 gather-aggregate of z ---------------------
// 16 nodes x 16 float4-chunks per 256-thread block
__global__ void __launch_bounds__(256) k_agg2(float* __restrict__ outp) {
    constexpr int F4 = 16, NPB = 16;
    __shared__ int s_start[NPB], s_deg[NPB];
    const int t  = threadIdx.x;
    const int n0 = blockIdx.x * NPB;
    if (t < NPB) {
        s_start[t] = g_row[n0 + t];
        s_deg[t]   = g_degi[n0 + t];
    }
    __syncthreads();
    int ni = t >> 4, c4 = t & 15;
    int st = s_start[ni], dg = s_deg[ni];
    const float4* z4 = (const float4*)g_z;
    float4 a0 = make_float4(0.f, 0.f, 0.f, 0.f);
    float4 a1 = a0, a2 = a0, a3 = a0;
    int j = 0;
    for (; j + 4 <= dg; j += 4) {
        int i0 = g_csr_src[st + j + 0];
        int i1 = g_csr_src[st + j + 1];
        int i2 = g_csr_src[st + j + 2];
        int i3 = g_csr_src[st + j + 3];
        float4 v0 = z4[(size_t)i0 * F4 + c4];
        float4 v1 = z4[(size_t)i1 * F4 + c4];
        float4 v2 = z4[(size_t)i2 * F4 + c4];
        float4 v3 = z4[(size_t)i3 * F4 + c4];
        a0.x += v0.x; a0.y += v0.y; a0.z += v0.z; a0.w += v0.w;
        a1.x += v1.x; a1.y += v1.y; a1.z += v1.z; a1.w += v1.w;
        a2.x += v2.x; a2.y += v2.y; a2.z += v2.z; a2.w += v2.w;
        a3.x += v3.x; a3.y += v3.y; a3.z += v3.z; a3.w += v3.w;
    }
    for (; j < dg; ++j) {
        float4 v = z4[(size_t)g_csr_src[st + j] * F4 + c4];
        a0.x += v.x; a0.y += v.y; a0.z += v.z; a0.w += v.w;
    }
    float inv = 1.f / fmaxf((float)dg, 1.f);
    float4* o4 = (float4*)outp;
    size_t oi = (size_t)(n0 + ni) * F4 + c4;
    float4 cur = o4[oi];
    cur.x += (a0.x + a1.x + a2.x + a3.x) * inv;
    cur.y += (a0.y + a1.y + a2.y + a3.y) * inv;
    cur.z += (a0.z + a1.z + a2.z + a3.z) * inv;
    cur.w += (a0.w + a1.w + a2.w + a3.w) * inv;
    o4[oi] = cur;
}

// ---------------- launch ----------------------------------------------------
extern "C" void kernel_launch(void* const* d_in, const int* in_sizes, int n_in,
                              void* d_out, int out_size) {
    const float* x   = (const float*)d_in[0];
    const void*  ei  = d_in[1];
    const float* w1l = (const float*)d_in[2];
    const float* b1  = (const float*)d_in[3];
    const float* w1r = (const float*)d_in[4];
    const float* w2l = (const float*)d_in[5];
    const float* b2  = (const float*)d_in[6];
    const float* w2r = (const float*)d_in[7];
    float*       out = (float*)d_out;

    k_init<<<NBLK, 256>>>((const int*)ei, w1l, w1r, w2l, w2r);
    k_deg<<<(E_EDGES / 2 + 255) / 256, 256>>>(ei);
    k_scanA<<<NBLK, 256>>>();
    k_scanB<<<1, 256>>>();
    k_scanC<<<NBLK, 256>>>();
    k_fill<<<(E_EDGES / 2 + 255) / 256, 256>>>(ei);
    k_sage1<<<N_NODES / 4, 128>>>(x, b1, b2, out);
    k_agg2<<<N_NODES / 16, 256>>>(out);
}